// round 1
// baseline (speedup 1.0000x reference)
#include <cuda_runtime.h>
#include <math.h>

// ---------------- problem constants ----------------
#define NN    50000
#define FIN   256
#define FOUT  128
#define HH    128
#define DD    16
#define EE    (NN*DD)     // 800000
#define G4    512         // 4*H

// ---------------- scratch (device globals; no allocation allowed) ----------------
__device__ float    g_proj[(size_t)NN*FOUT];   // 25.6MB
__device__ float    g_ssrc[NN];
__device__ float    g_strg[NN];
__device__ float    g_scores[EE];
__device__ unsigned g_gmax;
__device__ int      g_seqsrc[EE];
__device__ float    g_seqatt[EE];
__device__ float    g_wcat[G4*256];            // permuted [x|h] weights, 512KB
__device__ float    g_bcat[G4];

// ---------------- helpers ----------------
__device__ __forceinline__ unsigned fenc(float f) {
    unsigned i = __float_as_uint(f);
    return (i & 0x80000000u) ? ~i : (i | 0x80000000u);
}
__device__ __forceinline__ float fdec(unsigned u) {
    return (u & 0x80000000u) ? __uint_as_float(u ^ 0x80000000u) : __uint_as_float(~u);
}
__device__ __forceinline__ float sigmoidf(float x) { return 1.0f / (1.0f + expf(-x)); }

// ---------------- kernel: build permuted concat weights ----------------
// chunk ch (0..3) covers hidden dims [ch*32, ch*32+32); within a chunk,
// col c: gate = c/32 (i,f,g,o), dim = ch*32 + c%32. K: 0..127 = w_ih, 128..255 = w_hh.
__global__ void prep_w_k(const float* __restrict__ wih, const float* __restrict__ whh,
                         const float* __restrict__ bih, const float* __restrict__ bhh) {
    int idx = blockIdx.x * blockDim.x + threadIdx.x;   // 0..131071
    int R = idx >> 8;
    int k = idx & 255;
    int ch = R >> 7, c = R & 127;
    int gate = c >> 5, dd = c & 31;
    int grow = gate * 128 + ch * 32 + dd;
    float v = (k < 128) ? wih[grow * 128 + k] : whh[grow * 128 + (k - 128)];
    g_wcat[R * 256 + k] = v;
    if (k == 0) g_bcat[R] = bih[grow] + bhh[grow];
}

// ---------------- kernel: proj + skip fused GEMM ----------------
// out cols 0..127 -> g_proj (X @ Wp^T), cols 128..255 -> d_out (X @ Wsk^T)
__global__ void gemm1_k(const float* __restrict__ x, const float* __restrict__ Wp,
                        const float* __restrict__ Wsk, float* __restrict__ out) {
    __shared__ float xs[64 * 33];
    __shared__ float ws[256 * 33];
    int tid = threadIdx.x;
    int tx = tid & 15, ty = tid >> 4;
    int n0 = blockIdx.x * 64;
    float acc[4][16];
#pragma unroll
    for (int i = 0; i < 4; i++)
#pragma unroll
        for (int j = 0; j < 16; j++) acc[i][j] = 0.0f;

    for (int k0 = 0; k0 < 256; k0 += 32) {
        __syncthreads();
#pragma unroll
        for (int v = 0; v < 8; v++) {
            int idx = tid + v * 256;
            int r = idx >> 5, kk = idx & 31;
            int n = n0 + r;
            xs[r * 33 + kk] = (n < NN) ? x[(size_t)n * 256 + k0 + kk] : 0.0f;
        }
#pragma unroll
        for (int v = 0; v < 32; v++) {
            int idx = tid + v * 256;
            int c = idx >> 5, kk = idx & 31;
            ws[c * 33 + kk] = (c < 128) ? Wp[c * 256 + k0 + kk]
                                        : Wsk[(c - 128) * 256 + k0 + kk];
        }
        __syncthreads();
#pragma unroll
        for (int kk = 0; kk < 32; kk++) {
            float uv[4];
#pragma unroll
            for (int i = 0; i < 4; i++) uv[i] = xs[(ty * 4 + i) * 33 + kk];
#pragma unroll
            for (int j = 0; j < 16; j++) {
                float wv = ws[(tx + 16 * j) * 33 + kk];
#pragma unroll
                for (int i = 0; i < 4; i++) acc[i][j] = fmaf(uv[i], wv, acc[i][j]);
            }
        }
    }
#pragma unroll
    for (int i = 0; i < 4; i++) {
        int n = n0 + ty * 4 + i;
        if (n >= NN) continue;
#pragma unroll
        for (int j = 0; j < 16; j++) {
            int c = tx + 16 * j;
            if (c < 128) g_proj[(size_t)n * 128 + c] = acc[i][j];
            else         out[(size_t)n * 128 + (c - 128)] = acc[i][j];
        }
    }
}

// ---------------- kernel: per-node attention dots ----------------
__global__ void sdots_k(const float* __restrict__ as, const float* __restrict__ at) {
    int gtid = blockIdx.x * blockDim.x + threadIdx.x;
    int warp = gtid >> 5;
    int lane = gtid & 31;
    if (warp >= NN) return;
    const float* p = g_proj + (size_t)warp * 128;
    float s1 = 0.0f, s2 = 0.0f;
#pragma unroll
    for (int d = lane; d < 128; d += 32) {
        float v = p[d];
        s1 = fmaf(v, as[d], s1);
        s2 = fmaf(v, at[d], s2);
    }
#pragma unroll
    for (int o = 16; o; o >>= 1) {
        s1 += __shfl_xor_sync(0xffffffffu, s1, o);
        s2 += __shfl_xor_sync(0xffffffffu, s2, o);
    }
    if (lane == 0) { g_ssrc[warp] = s1; g_strg[warp] = s2; }
}

__global__ void initmax_k() { g_gmax = 0u; }

// ---------------- kernel: edge scores + global max ----------------
__global__ void scores_k(const int* __restrict__ ei) {
    int e = blockIdx.x * blockDim.x + threadIdx.x;   // EE = 3125*256 exact
    int s = ei[e];
    int t = ei[EE + e];
    float sc = g_ssrc[s] + g_strg[t];
    sc = (sc >= 0.0f) ? sc : 0.2f * sc;
    g_scores[e] = sc;
    float m = sc;
#pragma unroll
    for (int o = 16; o; o >>= 1) m = fmaxf(m, __shfl_xor_sync(0xffffffffu, m, o));
    __shared__ float wm[8];
    int lane = threadIdx.x & 31, wid = threadIdx.x >> 5;
    if (lane == 0) wm[wid] = m;
    __syncthreads();
    if (threadIdx.x == 0) {
        float mm = wm[0];
#pragma unroll
        for (int w = 1; w < 8; w++) mm = fmaxf(mm, wm[w]);
        atomicMax(&g_gmax, fenc(mm));
    }
}

// ---------------- kernel: softmax + stable sort (desc att, tie -> desc idx) ----------------
__global__ void sort_k(const int* __restrict__ ei) {
    int n = blockIdx.x * blockDim.x + threadIdx.x;
    if (n >= NN) return;
    float gmax = fdec(g_gmax);
    float ev[DD], srt[DD];
    int idx[DD];
    float denom = 0.0f;
#pragma unroll
    for (int j = 0; j < DD; j++) {
        float e = expf(g_scores[n * DD + j] - gmax);
        ev[j] = e;
        denom += e;
    }
    denom += 1e-16f;
    // insertion sort, descending; "<=" shift => later (larger) original index first on ties,
    // matching stable-ascending argsort followed by reversal.
    for (int j = 0; j < DD; j++) {
        float key = ev[j];
        int pos = j;
        while (pos > 0 && srt[pos - 1] <= key) {
            srt[pos] = srt[pos - 1];
            idx[pos] = idx[pos - 1];
            pos--;
        }
        srt[pos] = key;
        idx[pos] = j;
    }
    float inv = 1.0f / denom;
#pragma unroll
    for (int t = 0; t < DD; t++) {
        int j = idx[t];
        g_seqsrc[n * DD + t] = ei[n * DD + j];     // src of edge
        g_seqatt[n * DD + t] = srt[t] * inv;
    }
}

// ---------------- kernel: backward-direction LSTM + epilogue ----------------
// 64 nodes per block. u = [x_t | h] in SMEM (stride 257). Per timestep, 4 chunks;
// each chunk computes 128 gate cols = (i,f,g,o) x 32 hidden dims, then updates c,h.
#define LSTM_SMEM_FLOATS (64*257 + 3*64*129 + 128*33)

__global__ __launch_bounds__(256, 1) void lstm_k(const float* __restrict__ bias,
                                                 float* __restrict__ out) {
    extern __shared__ float sm[];
    float* u   = sm;                 // [64][257]  cols 0..127 x_t, 128..255 h
    float* csm = u + 64 * 257;       // [64][129]
    float* gb  = csm + 64 * 129;     // [64][129]  gate staging for current chunk
    float* hn  = gb + 64 * 129;      // [64][129]  new h
    float* wsm = hn + 64 * 129;      // [128][33]  weight tile

    int tid = threadIdx.x;
    int tx = tid & 15, ty = tid >> 4;
    int n0 = blockIdx.x * 64;

    // init: x_0 gather, h=0, c=0
    for (int idx = tid; idx < 64 * 128; idx += 256) {
        int r = idx >> 7, d = idx & 127;
        int n = n0 + r;
        float xv = 0.0f;
        if (n < NN) {
            int s = g_seqsrc[n * DD + 0];
            float a = g_seqatt[n * DD + 0];
            xv = g_proj[(size_t)s * 128 + d] * a;
        }
        u[r * 257 + d] = xv;
        u[r * 257 + 128 + d] = 0.0f;
        csm[r * 129 + d] = 0.0f;
    }
    __syncthreads();

    for (int t = 0; t < DD; t++) {
#pragma unroll 1
        for (int ch = 0; ch < 4; ch++) {
            float acc[4][8];
#pragma unroll
            for (int i = 0; i < 4; i++)
#pragma unroll
                for (int j = 0; j < 8; j++) acc[i][j] = 0.0f;

#pragma unroll 1
            for (int k0 = 0; k0 < 256; k0 += 32) {
                __syncthreads();
#pragma unroll
                for (int v = 0; v < 16; v++) {
                    int idx = tid + v * 256;
                    int c = idx >> 5, kk = idx & 31;
                    wsm[c * 33 + kk] = g_wcat[(ch * 128 + c) * 256 + k0 + kk];
                }
                __syncthreads();
#pragma unroll
                for (int kk = 0; kk < 32; kk++) {
                    float uv[4];
#pragma unroll
                    for (int i = 0; i < 4; i++) uv[i] = u[(ty * 4 + i) * 257 + k0 + kk];
#pragma unroll
                    for (int j = 0; j < 8; j++) {
                        float wv = wsm[(tx + 16 * j) * 33 + kk];
#pragma unroll
                        for (int i = 0; i < 4; i++) acc[i][j] = fmaf(uv[i], wv, acc[i][j]);
                    }
                }
            }
            __syncthreads();
#pragma unroll
            for (int i = 0; i < 4; i++)
#pragma unroll
                for (int j = 0; j < 8; j++) {
                    int c = tx + 16 * j;
                    gb[(ty * 4 + i) * 129 + c] = acc[i][j] + g_bcat[ch * 128 + c];
                }
            __syncthreads();
            // c/h update for hidden dims ch*32 .. ch*32+31
            for (int idx = tid; idx < 64 * 32; idx += 256) {
                int r = idx >> 5, dd2 = idx & 31;
                int d = ch * 32 + dd2;
                float ig = sigmoidf(gb[r * 129 + dd2]);
                float fg = sigmoidf(gb[r * 129 + 32 + dd2]);
                float gg = tanhf(gb[r * 129 + 64 + dd2]);
                float og = sigmoidf(gb[r * 129 + 96 + dd2]);
                float c_ = fg * csm[r * 129 + d] + ig * gg;
                csm[r * 129 + d] = c_;
                hn[r * 129 + d] = og * tanhf(c_);
            }
            __syncthreads();
        }
        if (t < DD - 1) {
            for (int idx = tid; idx < 64 * 128; idx += 256) {
                int r = idx >> 7, d = idx & 127;
                int n = n0 + r;
                u[r * 257 + 128 + d] = hn[r * 129 + d];
                float xv = 0.0f;
                if (n < NN) {
                    int s = g_seqsrc[n * DD + t + 1];
                    float a = g_seqatt[n * DD + t + 1];
                    xv = g_proj[(size_t)s * 128 + d] * a;
                }
                u[r * 257 + d] = xv;
            }
            __syncthreads();
        } else {
            for (int idx = tid; idx < 64 * 128; idx += 256) {
                int r = idx >> 7, d = idx & 127;
                int n = n0 + r;
                if (n < NN) {
                    float v = hn[r * 129 + d] + out[(size_t)n * 128 + d] + bias[d];
                    out[(size_t)n * 128 + d] = (v >= 0.0f) ? v : 0.01f * v;
                }
            }
        }
    }
}

// ---------------- launch ----------------
extern "C" void kernel_launch(void* const* d_in, const int* in_sizes, int n_in,
                              void* d_out, int out_size) {
    const float* x    = (const float*)d_in[0];
    const float* Wp   = (const float*)d_in[1];
    const float* asrc = (const float*)d_in[2];
    const float* atrg = (const float*)d_in[3];
    const float* Wsk  = (const float*)d_in[4];
    const float* bias = (const float*)d_in[5];
    // d_in[6..9]: forward-direction weights, unused by the reference
    const float* wihb = (const float*)d_in[10];
    const float* whhb = (const float*)d_in[11];
    const float* bihb = (const float*)d_in[12];
    const float* bhhb = (const float*)d_in[13];
    const int*   ei   = (const int*)d_in[14];
    float* out = (float*)d_out;

    (void)in_sizes; (void)n_in; (void)out_size;

    cudaFuncSetAttribute(lstm_k, cudaFuncAttributeMaxDynamicSharedMemorySize,
                         LSTM_SMEM_FLOATS * (int)sizeof(float));

    prep_w_k<<<512, 256>>>(wihb, whhb, bihb, bhhb);
    gemm1_k<<<(NN + 63) / 64, 256>>>(x, Wp, Wsk, out);
    sdots_k<<<(NN * 32 + 255) / 256, 256>>>(asrc, atrg);
    initmax_k<<<1, 1>>>();
    scores_k<<<EE / 256, 256>>>(ei);
    sort_k<<<(NN + 255) / 256, 256>>>(ei);
    lstm_k<<<(NN + 63) / 64, 256, LSTM_SMEM_FLOATS * (int)sizeof(float)>>>(bias, out);
}